// round 4
// baseline (speedup 1.0000x reference)
#include <cuda_runtime.h>
#include <cstdint>

// PlaceCellNetwork: 50 fixed-point iterations of
//   z_j = C_j + sum_i max(z_i,0) * G[i][j],  Y_j = inv_j * max(z_j, 0)
// Early exit never fires (||Y50-Y49||/||Y|| ~ 3.5e-3 > tol): exactly 50 iterations.
// Rows independent; one row per thread; j-packed fma.rn.f32x2 (rt=2, pair-native RF reads).
// R4: R3 body (C-fold + MOV-free reludup) at NATURAL register count (no occupancy clamp
// -> no spills), plus grid-stride persistent launch (3 blocks/SM resident) to kill
// wave-quantization tail and amortize the G prologue.

#define DT    0.05f
#define LBD1  0.005f
#define LBD2  0.005f
#define NITER 50

__device__ __align__(16) float g_G2[100];  // (i*5+p)*2 -> {G[i][2p], G[i][2p+1]}
__device__ __align__(16) float g_W2[52];   // (k*5+p)*2 -> {dt*W[2p][k], dt*W[2p+1][k]}
__device__ __align__(16) float g_C0[12];   // C0_j = -dt*b_j - lbd1
__device__ __align__(16) float g_inv[12];  // 1/(lbd2 + M[j][j])

__global__ void setup_kernel(const float* __restrict__ W,
                             const float* __restrict__ M,
                             const float* __restrict__ b) {
    int t = threadIdx.x;
    if (t < 100) {
        int q = t >> 1, half = t & 1;
        int i = q / 5, p = q % 5, j = 2 * p + half;
        float H = (i == j) ? (1.0f - DT) : (-DT * M[i * 10 + j]);
        g_G2[t] = H / (LBD2 + M[i * 10 + i]);
    }
    if (t < 50) {
        int q = t >> 1, half = t & 1;
        int k = q / 5, p = q % 5, j = 2 * p + half;
        g_W2[t] = DT * W[j * 5 + k];
    }
    if (t < 10) {
        g_C0[t]  = -DT * b[t] - LBD1;
        g_inv[t] = 1.0f / (LBD2 + M[t * 10 + t]);
    }
}

typedef unsigned long long u64;

__device__ __forceinline__ u64 f2fma(u64 a, u64 b, u64 c) {
    u64 d;
    asm("fma.rn.f32x2 %0, %1, %2, %3;" : "=l"(d) : "l"(a), "l"(b), "l"(c));
    return d;
}
__device__ __forceinline__ u64 f2pack(float lo, float hi) {
    u64 d;
    asm("mov.b64 %0, {%1, %2};" : "=l"(d) : "f"(lo), "f"(hi));
    return d;
}
__device__ __forceinline__ void f2unpack(u64 v, float& lo, float& hi) {
    asm("mov.b64 {%0, %1}, %2;" : "=f"(lo), "=f"(hi) : "l"(v));
}
// Duplicated relu pair without a MOV: {max(x,+0), max(x,-0)} — two distinct FMNMX
// (not CSE-able); the -0 half is arithmetically inert as an FMA multiplier.
// Verified bit-identical to the MOV version in R3 (same rel_err to the last digit).
__device__ __forceinline__ u64 reludup(float x) {
    return f2pack(fmaxf(x, 0.0f), fmaxf(x, -0.0f));
}

__global__ __launch_bounds__(128)
void pcn_kernel(const float* __restrict__ X, float* __restrict__ Yout, int rows) {
    // Folded coupling matrix, register-resident, loaded once per thread lifetime
    const u64* G2p = (const u64*)g_G2;
    u64 G[50];
#pragma unroll
    for (int q = 0; q < 50; q++) G[q] = G2p[q];

    const u64* C0p = (const u64*)g_C0;
    const u64* W2p = (const u64*)g_W2;
    float2* out = (float2*)Yout;

    int stride = gridDim.x * blockDim.x;
    for (int r = blockIdx.x * blockDim.x + threadIdx.x; r < rows; r += stride) {
        // Row input
        float x[5];
#pragma unroll
        for (int k = 0; k < 5; k++) x[k] = X[(size_t)r * 5 + k];

        // C = C0 + (x,x)*W2  (init folded into k=0 FMA)
        u64 C2[5];
        {
            u64 xd0 = f2pack(x[0], x[0]);
#pragma unroll
            for (int p = 0; p < 5; p++) C2[p] = f2fma(xd0, W2p[p], C0p[p]);
#pragma unroll
            for (int k = 1; k < 5; k++) {
                u64 xd = f2pack(x[k], x[k]);
#pragma unroll
                for (int p = 0; p < 5; p++)
                    C2[p] = f2fma(xd, W2p[k * 5 + p], C2[p]);
            }
        }

        // z^(1) = C
        u64 z[5];
#pragma unroll
        for (int p = 0; p < 5; p++) z[p] = C2[p];

        // 49 more updates: Vd = reludup(z); z = C + V*G with C folded into i=0 FMA
#pragma unroll 1
        for (int it = 0; it < NITER - 1; it++) {
            u64 Vd[10];
#pragma unroll
            for (int p = 0; p < 5; p++) {
                float lo, hi;
                f2unpack(z[p], lo, hi);
                Vd[2 * p]     = reludup(lo);
                Vd[2 * p + 1] = reludup(hi);
            }
#pragma unroll
            for (int p = 0; p < 5; p++)
                z[p] = f2fma(Vd[0], G[p], C2[p]);
#pragma unroll
            for (int i = 1; i < 10; i++) {
#pragma unroll
                for (int p = 0; p < 5; p++)
                    z[p] = f2fma(Vd[i], G[i * 5 + p], z[p]);
            }
        }

        // Final activation + per-output scale; 8-byte vector stores (rows 40B -> 8B aligned)
#pragma unroll
        for (int p = 0; p < 5; p++) {
            float lo, hi;
            f2unpack(z[p], lo, hi);
            float2 y;
            y.x = fmaxf(lo, 0.0f) * g_inv[2 * p];
            y.y = fmaxf(hi, 0.0f) * g_inv[2 * p + 1];
            out[(size_t)r * 5 + p] = y;
        }
    }
}

extern "C" void kernel_launch(void* const* d_in, const int* in_sizes, int n_in,
                              void* d_out, int out_size) {
    // Identify inputs by element count: X=B*5, W=50, M=100, b=10
    const float *X = nullptr, *W = nullptr, *M = nullptr, *b = nullptr;
    int rows = 0;
    for (int i = 0; i < n_in; i++) {
        int s = in_sizes[i];
        const float* p = (const float*)d_in[i];
        if (s == 100) M = p;
        else if (s == 50) W = p;
        else if (s == 10) b = p;
        else { X = p; rows = s / 5; }
    }

    setup_kernel<<<1, 128>>>(W, M, b);

    // Persistent grid: 3 resident blocks per SM (168 regs x 128 thr), grid-stride over rows.
    // 456 = 152 SM (GB300) x 3; correct for any SM count via the stride loop.
    const int threads = 128;
    int blocks = 456;
    int max_blocks = (rows + threads - 1) / threads;
    if (blocks > max_blocks) blocks = max_blocks;
    pcn_kernel<<<blocks, threads>>>(X, (float*)d_out, rows);
}

// round 5
// speedup vs baseline: 1.1487x; 1.1487x over previous
#include <cuda_runtime.h>
#include <cstdint>

// PlaceCellNetwork: 50 fixed-point iterations of
//   z_j = C_j + sum_i max(z_i,0) * G[i][j],  Y_j = inv_j * max(z_j, 0)
// Early exit never fires: exactly 50 iterations; rows independent.
// R5: G lives in SHARED memory (broadcast LDS.128, conflict-free) instead of 100
// registers -> per-thread state ~100 regs -> room for 2 rows/thread (real ILP this
// time) at 4 blocks/SM. One LDS.128 feeds 4 FFMA2 (2 G-pairs x 2 rows).
// j-packed fma.rn.f32x2 throughout; accumulation order identical to R1 (rel_err 8e-7).

#define DT    0.05f
#define LBD1  0.005f
#define LBD2  0.005f
#define NITER 50

__device__ __align__(16) float g_G2[104];  // (i*5+p)*2 -> {G[i][2p], G[i][2p+1]} (+pad)
__device__ __align__(16) float g_W2[52];   // (k*5+p)*2 -> {dt*W[2p][k], dt*W[2p+1][k]}
__device__ __align__(16) float g_C0[12];   // C0_j = -dt*b_j - lbd1
__device__ __align__(16) float g_inv[12];  // 1/(lbd2 + M[j][j])

__global__ void setup_kernel(const float* __restrict__ W,
                             const float* __restrict__ M,
                             const float* __restrict__ b) {
    int t = threadIdx.x;
    if (t < 100) {
        int q = t >> 1, half = t & 1;
        int i = q / 5, p = q % 5, j = 2 * p + half;
        float H = (i == j) ? (1.0f - DT) : (-DT * M[i * 10 + j]);
        g_G2[t] = H / (LBD2 + M[i * 10 + i]);
    }
    if (t >= 100 && t < 104) g_G2[t] = 0.0f;  // pad (loaded, never used)
    if (t < 50) {
        int q = t >> 1, half = t & 1;
        int k = q / 5, p = q % 5, j = 2 * p + half;
        g_W2[t] = DT * W[j * 5 + k];
    }
    if (t < 10) {
        g_C0[t]  = -DT * b[t] - LBD1;
        g_inv[t] = 1.0f / (LBD2 + M[t * 10 + t]);
    }
}

typedef unsigned long long u64;

__device__ __forceinline__ u64 f2fma(u64 a, u64 b, u64 c) {
    u64 d;
    asm("fma.rn.f32x2 %0, %1, %2, %3;" : "=l"(d) : "l"(a), "l"(b), "l"(c));
    return d;
}
__device__ __forceinline__ u64 f2pack(float lo, float hi) {
    u64 d;
    asm("mov.b64 %0, {%1, %2};" : "=l"(d) : "f"(lo), "f"(hi));
    return d;
}
__device__ __forceinline__ void f2unpack(u64 v, float& lo, float& hi) {
    asm("mov.b64 {%0, %1}, %2;" : "=f"(lo), "=f"(hi) : "l"(v));
}
// Duplicated relu pair without a MOV: {max(x,+0), max(x,-0)} — two distinct FMNMX;
// the -0 half is arithmetically inert as an FMA multiplier. Bit-identical (R3/R4).
__device__ __forceinline__ u64 reludup(float x) {
    return f2pack(fmaxf(x, 0.0f), fmaxf(x, -0.0f));
}

__global__ __launch_bounds__(128, 4)
void pcn_kernel(const float* __restrict__ X, float* __restrict__ Yout,
                int half, int rows) {
    // Folded coupling matrix in shared memory (broadcast reads, conflict-free)
    __shared__ __align__(16) u64 sG[52];
    int t = threadIdx.x;
    if (t < 26) ((ulonglong2*)sG)[t] = ((const ulonglong2*)g_G2)[t];
    __syncthreads();

    int r = blockIdx.x * blockDim.x + t;
    if (r >= half) return;
    int r2 = r + half;
    if (r2 >= rows) r2 = r;   // odd row count guard; benign duplicate

    // Row inputs (coalesced: consecutive threads -> consecutive rows, both streams)
    float xa[5], xb[5];
#pragma unroll
    for (int k = 0; k < 5; k++) xa[k] = X[(size_t)r  * 5 + k];
#pragma unroll
    for (int k = 0; k < 5; k++) xb[k] = X[(size_t)r2 * 5 + k];

    // C = C0 + (x,x)*W2  (k=0 folds the init)
    const u64* C0p = (const u64*)g_C0;
    const u64* W2p = (const u64*)g_W2;
    u64 Ca[5], Cb[5];
    {
        u64 xd0a = f2pack(xa[0], xa[0]);
        u64 xd0b = f2pack(xb[0], xb[0]);
#pragma unroll
        for (int p = 0; p < 5; p++) {
            Ca[p] = f2fma(xd0a, W2p[p], C0p[p]);
            Cb[p] = f2fma(xd0b, W2p[p], C0p[p]);
        }
#pragma unroll
        for (int k = 1; k < 5; k++) {
            u64 xda = f2pack(xa[k], xa[k]);
            u64 xdb = f2pack(xb[k], xb[k]);
#pragma unroll
            for (int p = 0; p < 5; p++) {
                Ca[p] = f2fma(xda, W2p[k * 5 + p], Ca[p]);
                Cb[p] = f2fma(xdb, W2p[k * 5 + p], Cb[p]);
            }
        }
    }

    // z^(1) = C
    u64 za[5], zb[5];
#pragma unroll
    for (int p = 0; p < 5; p++) { za[p] = Ca[p]; zb[p] = Cb[p]; }

    const ulonglong2* sG2 = (const ulonglong2*)sG;

    // 49 more updates. V = reludup(z); z = C + V*G (C folded into i=0 FMAs).
    // One LDS.128 delivers two G pairs -> 4 FFMA2 (2 pairs x 2 rows).
#pragma unroll 1
    for (int it = 0; it < NITER - 1; it++) {
        u64 Va[10], Vb[10];
#pragma unroll
        for (int p = 0; p < 5; p++) {
            float lo, hi;
            f2unpack(za[p], lo, hi);
            Va[2 * p]     = reludup(lo);
            Va[2 * p + 1] = reludup(hi);
            f2unpack(zb[p], lo, hi);
            Vb[2 * p]     = reludup(lo);
            Vb[2 * p + 1] = reludup(hi);
        }
#pragma unroll
        for (int q = 0; q < 25; q++) {
            ulonglong2 g = sG2[q];
            {
                const int f = 2 * q, i = f / 5, p = f % 5;
                if (i == 0) {
                    za[p] = f2fma(Va[0], g.x, Ca[p]);
                    zb[p] = f2fma(Vb[0], g.x, Cb[p]);
                } else {
                    za[p] = f2fma(Va[i], g.x, za[p]);
                    zb[p] = f2fma(Vb[i], g.x, zb[p]);
                }
            }
            {
                const int f = 2 * q + 1, i = f / 5, p = f % 5;
                if (i == 0) {
                    za[p] = f2fma(Va[0], g.y, Ca[p]);
                    zb[p] = f2fma(Vb[0], g.y, Cb[p]);
                } else {
                    za[p] = f2fma(Va[i], g.y, za[p]);
                    zb[p] = f2fma(Vb[i], g.y, zb[p]);
                }
            }
        }
    }

    // Final activation + per-output scale; 8-byte vector stores (rows 40B -> 8B aligned)
    float2* out = (float2*)Yout;
#pragma unroll
    for (int p = 0; p < 5; p++) {
        float lo, hi;
        f2unpack(za[p], lo, hi);
        float2 y;
        y.x = fmaxf(lo, 0.0f) * g_inv[2 * p];
        y.y = fmaxf(hi, 0.0f) * g_inv[2 * p + 1];
        out[(size_t)r * 5 + p] = y;
        f2unpack(zb[p], lo, hi);
        y.x = fmaxf(lo, 0.0f) * g_inv[2 * p];
        y.y = fmaxf(hi, 0.0f) * g_inv[2 * p + 1];
        out[(size_t)r2 * 5 + p] = y;
    }
}

extern "C" void kernel_launch(void* const* d_in, const int* in_sizes, int n_in,
                              void* d_out, int out_size) {
    // Identify inputs by element count: X=B*5, W=50, M=100, b=10
    const float *X = nullptr, *W = nullptr, *M = nullptr, *b = nullptr;
    int rows = 0;
    for (int i = 0; i < n_in; i++) {
        int s = in_sizes[i];
        const float* p = (const float*)d_in[i];
        if (s == 100) M = p;
        else if (s == 50) W = p;
        else if (s == 10) b = p;
        else { X = p; rows = s / 5; }
    }

    setup_kernel<<<1, 128>>>(W, M, b);

    int half = (rows + 1) / 2;
    const int threads = 128;
    int blocks = (half + threads - 1) / threads;
    pcn_kernel<<<blocks, threads>>>(X, (float*)d_out, half, rows);
}